// round 4
// baseline (speedup 1.0000x reference)
#include <cuda_runtime.h>
#include <math.h>

#define NB 64
#define NA 8732
#define NA4 2183            // NA/4 (exact)
#define NA4P 2560           // padded to 5*512
#define NAP 9216            // padded to 18*512
#define NG 50
#define NC 21
#define NBX 35              // ceil(NA/256)
#define IOU_THR 0.5f
#define VXY 0.1f
#define VWH 0.2f
#define EPS16 9.765625e-4

// ---------------- device scratch (no allocations allowed) ----------------
__device__ float  g_lossneg[NB * NA];     // ce for negatives, -1 sentinel for positives
__device__ float  g_psl1[NB * NBX];
__device__ float  g_pce [NB * NBX];
__device__ int    g_pnp [NB * NBX];
__device__ double g_ob_cp[NB];
__device__ double g_ob_cn[NB];
__device__ double g_ob_np[NB];
__device__ double g_ob_sl[NB];
__device__ int    g_ctr;

// ---------------- helpers ----------------
__device__ __forceinline__ double warpRedD(double v) {
    #pragma unroll
    for (int o = 16; o > 0; o >>= 1) v += __shfl_down_sync(0xFFFFFFFFu, v, o);
    return v;
}
__device__ __forceinline__ float warpRedF(float v) {
    #pragma unroll
    for (int o = 16; o > 0; o >>= 1) v += __shfl_down_sync(0xFFFFFFFFu, v, o);
    return v;
}
__device__ __forceinline__ float smoothL1(float d) {
    float ad = fabsf(d);
    return ad < 1.0f ? 0.5f * d * d : ad - 0.5f;
}
__device__ __forceinline__ unsigned ordkey(float f) {
    unsigned u = __float_as_uint(f);
    return u ^ ((u >> 31) ? 0xFFFFFFFFu : 0x80000000u);
}
__device__ __forceinline__ float ordval(unsigned k) {
    unsigned u = (k & 0x80000000u) ? (k ^ 0x80000000u) : ~k;
    return __uint_as_float(u);
}
// warp-aggregated histogram add: lanes with equal bin combine into one atomic
__device__ __forceinline__ void aggAdd(unsigned* hist, unsigned bin, bool valid, int lane) {
    unsigned key = valid ? bin : 0xFFFFFFFFu;
    unsigned m = __match_any_sync(0xFFFFFFFFu, key);
    int leader = __ffs(m) - 1;
    if (valid && lane == leader) atomicAdd(&hist[bin], (unsigned)__popc(m));
}

// ---------------- kernel 1: match + box loss + CE ----------------
__global__ __launch_bounds__(256) void k_match(const float* __restrict__ preg,
                        const float* __restrict__ pcls,
                        const float* __restrict__ ancs,
                        const float* __restrict__ gbox,
                        const int*   __restrict__ glab) {
    const int b = blockIdx.y;
    const int a = blockIdx.x * 256 + threadIdx.x;

    __shared__ float4 s_gb[NG];
    __shared__ float  s_ga[NG];
    __shared__ int    s_gl[NG];
    if (threadIdx.x < NG) {
        float4 gb = reinterpret_cast<const float4*>(gbox)[b * NG + threadIdx.x];
        int    gl = glab[b * NG + threadIdx.x];
        float  ag = (gb.z - gb.x) * (gb.w - gb.y);
        if (gl <= 0) { gb = make_float4(0.f, 0.f, 0.f, 0.f); ag = 0.f; }  // iou -> 0
        s_gb[threadIdx.x] = gb;
        s_ga[threadIdx.x] = ag;
        s_gl[threadIdx.x] = gl;
    }
    __syncthreads();

    float sl1_c = 0.f, ce_c = 0.f;
    int pos_c = 0;

    if (a < NA) {
        float4 anc = reinterpret_cast<const float4*>(ancs)[a];
        float al = anc.x - anc.z * 0.5f;
        float at = anc.y - anc.w * 0.5f;
        float ar = anc.x + anc.z * 0.5f;
        float ab = anc.y + anc.w * 0.5f;
        float area_a = (ar - al) * (ab - at);

        // division-free IoU argmax: keep (inter, union) of current best
        float inb = -1.0f, unb = 1.0f;
        int   bi  = 0;
        #pragma unroll 10
        for (int g = 0; g < NG; g++) {
            float4 gb = s_gb[g];
            float ltx = fmaxf(gb.x, al), lty = fmaxf(gb.y, at);
            float rbx = fminf(gb.z, ar), rby = fminf(gb.w, ab);
            float w = fmaxf(rbx - ltx, 0.0f), h = fmaxf(rby - lty, 0.0f);
            float inter = w * h;
            float uni = fmaxf(s_ga[g] + area_a - inter, 1e-8f);
            if (inter * unb > inb * uni) { inb = inter; unb = uni; bi = g; }
        }
        bool pos = (2.0f * inb >= unb);   // iou >= 0.5

        float4 gb = s_gb[bi];
        float gcx = (gb.x + gb.z) * 0.5f, gcy = (gb.y + gb.w) * 0.5f;
        float gw = gb.z - gb.x, gh = gb.w - gb.y;
        float tx = (gcx - anc.x) / (anc.z * VXY);
        float ty = (gcy - anc.y) / (anc.w * VXY);
        float tw = __logf(fmaxf(gw, 1e-6f) / anc.z) * (1.0f / VWH);
        float th = __logf(fmaxf(gh, 1e-6f) / anc.w) * (1.0f / VWH);
        float d0 = preg[(b * 4 + 0) * NA + a] - tx;
        float d1 = preg[(b * 4 + 1) * NA + a] - ty;
        float d2 = preg[(b * 4 + 2) * NA + a] - tw;
        float d3 = preg[(b * 4 + 3) * NA + a] - th;
        float sl1 = smoothL1(d0) + smoothL1(d1) + smoothL1(d2) + smoothL1(d3);

        float xs[NC];
        float m = -1e30f;
        #pragma unroll
        for (int c = 0; c < NC; c++) {
            xs[c] = pcls[(b * NC + c) * NA + a];
            m = fmaxf(m, xs[c]);
        }
        float s = 0.0f;
        #pragma unroll
        for (int c = 0; c < NC; c++) s += __expf(xs[c] - m);
        float lse = m + __logf(s);
        int lab = pos ? s_gl[bi] : 0;
        float ce = lse - xs[lab];

        g_lossneg[b * NA + a] = pos ? -1.0f : ce;
        if (pos) { pos_c = 1; ce_c = ce; sl1_c = sl1; }
    }

    sl1_c = warpRedF(sl1_c);
    ce_c  = warpRedF(ce_c);
    float posf = warpRedF((float)pos_c);
    __shared__ float sh0[8], sh1[8], sh2[8];
    int wid = threadIdx.x >> 5, lid = threadIdx.x & 31;
    if (lid == 0) { sh0[wid] = sl1_c; sh1[wid] = ce_c; sh2[wid] = posf; }
    __syncthreads();
    if (wid == 0) {
        float v0 = (lid < 8) ? sh0[lid] : 0.f;
        float v1 = (lid < 8) ? sh1[lid] : 0.f;
        float v2 = (lid < 8) ? sh2[lid] : 0.f;
        v0 = warpRedF(v0); v1 = warpRedF(v1); v2 = warpRedF(v2);
        if (lid == 0) {
            int p = b * NBX + blockIdx.x;
            g_psl1[p] = v0;
            g_pce [p] = v1;
            g_pnp [p] = (int)(v2 + 0.5f);
        }
    }
}

// ---------------- kernel 2: smem-staged radix top-K + final combine ----------------
__global__ __launch_bounds__(512) void k_select(float* __restrict__ out) {
    const int b = blockIdx.x;
    const int tid = threadIdx.x;
    const int lane = tid & 31;

    __shared__ __align__(16) unsigned s_keys[NA];
    __shared__ unsigned hist[256];
    __shared__ unsigned s_suf[256];
    __shared__ unsigned s_wsum[8];
    __shared__ unsigned s_bin;
    __shared__ int s_rem;
    __shared__ double s_np, s_ce, s_sl;
    __shared__ int s_ticket;
    __shared__ double sd[16];

    if (tid < 256) hist[tid] = 0;
    if (tid >= 256 && tid < 288) {
        int t = tid - 256;
        double np = 0.0, ce = 0.0, sl = 0.0;
        for (int i = t; i < NBX; i += 32) {
            int p = b * NBX + i;
            np += (double)g_pnp[p];
            ce += (double)g_pce[p];
            sl += (double)g_psl1[p];
        }
        np = warpRedD(np); ce = warpRedD(ce); sl = warpRedD(sl);
        if (t == 0) { s_np = np; s_ce = ce; s_sl = sl; }
    }
    __syncthreads();

    // pass 1: vectorized global read -> smem keys + aggregated top-byte histogram
    const float4* base4 = reinterpret_cast<const float4*>(&g_lossneg[b * NA]);
    uint4* keys4 = reinterpret_cast<uint4*>(s_keys);
    for (int i = tid; i < NA4P; i += 512) {
        bool valid = (i < NA4);
        unsigned k0 = 0, k1 = 0, k2 = 0, k3 = 0;
        if (valid) {
            float4 v = base4[i];
            k0 = ordkey(v.x); k1 = ordkey(v.y); k2 = ordkey(v.z); k3 = ordkey(v.w);
            keys4[i] = make_uint4(k0, k1, k2, k3);
        }
        aggAdd(hist, k0 >> 24, valid, lane);
        aggAdd(hist, k1 >> 24, valid, lane);
        aggAdd(hist, k2 >> 24, valid, lane);
        aggAdd(hist, k3 >> 24, valid, lane);
    }
    __syncthreads();

    int npos = (int)(s_np + 0.5);
    int numneg = NA - npos;
    int K = (npos > 0) ? min(3 * npos, numneg) : (numneg > 0 ? 1 : 0);

    double negsum = 0.0;
    if (K > 0) {
        unsigned prefix = 0, hmask = 0;
        int remaining = K;

        for (int shift = 24; shift >= 0; shift -= 8) {
            if (shift != 24) {
                if (tid < 256) hist[tid] = 0;
                __syncthreads();
                for (int i = tid; i < NAP; i += 512) {
                    bool valid = false;
                    unsigned bin = 0;
                    if (i < NA) {
                        unsigned u = s_keys[i];
                        valid = ((u & hmask) == prefix);
                        bin = (u >> shift) & 255u;
                    }
                    aggAdd(hist, bin, valid, lane);
                }
                __syncthreads();
            }

            // parallel inclusive suffix scan over 256 bins
            unsigned v = 0;
            if (tid < 256) {
                v = hist[tid];
                #pragma unroll
                for (int d = 1; d < 32; d <<= 1) {
                    unsigned t = __shfl_down_sync(0xFFFFFFFFu, v, d);
                    if (lane + d < 32) v += t;
                }
                if (lane == 0) s_wsum[tid >> 5] = v;
            }
            __syncthreads();
            if (tid < 256) {
                int w = tid >> 5;
                unsigned e = 0;
                #pragma unroll
                for (int j = 0; j < 8; j++) if (j > w) e += s_wsum[j];
                s_suf[tid] = v + e;
            }
            __syncthreads();
            if (tid < 256) {
                unsigned sufn = (tid < 255) ? s_suf[tid + 1] : 0u;
                unsigned suf  = s_suf[tid];
                unsigned rem  = (unsigned)remaining;
                if (sufn < rem && rem <= suf) { s_bin = (unsigned)tid; s_rem = (int)(rem - sufn); }
            }
            __syncthreads();
            prefix |= (s_bin << shift);
            hmask  |= (255u << shift);
            remaining = s_rem;
            __syncthreads();
        }

        unsigned pivot = prefix;
        float pv = ordval(pivot);

        double s = 0.0;
        for (int i = tid; i < NA; i += 512) {
            unsigned u = s_keys[i];
            if (u > pivot) s += (double)ordval(u);
        }
        s = warpRedD(s);
        if (lane == 0) sd[tid >> 5] = s;
        __syncthreads();
        if (tid < 32) {
            double t = (tid < 16) ? sd[tid] : 0.0;
            t = warpRedD(t);
            if (tid == 0) sd[0] = t + (double)remaining * (double)pv;
        }
        __syncthreads();
        negsum = sd[0];
    }

    if (tid == 0) {
        double nums = fmax(s_np, (double)EPS16);
        g_ob_cp[b] = s_ce / nums;
        g_ob_cn[b] = negsum / nums;
        g_ob_np[b] = s_np;
        g_ob_sl[b] = s_sl;
        __threadfence();
        s_ticket = atomicAdd(&g_ctr, 1);
    }
    __syncthreads();

    if (s_ticket == NB - 1) {
        double cp = 0.0, cn = 0.0, np = 0.0, sl = 0.0;
        if (tid < NB) {
            cp = g_ob_cp[tid]; cn = g_ob_cn[tid];
            np = g_ob_np[tid]; sl = g_ob_sl[tid];
        }
        cp = warpRedD(cp); cn = warpRedD(cn); np = warpRedD(np); sl = warpRedD(sl);
        __shared__ double f0[2], f1[2], f2[2], f3[2];
        if (lane == 0 && tid < NB) {
            f0[tid >> 5] = cp; f1[tid >> 5] = cn; f2[tid >> 5] = np; f3[tid >> 5] = sl;
        }
        __syncthreads();
        if (tid == 0) {
            double CP = f0[0] + f0[1];
            double CN = f1[0] + f1[1];
            double NP = f2[0] + f2[1];
            double SL = f3[0] + f3[1];
            double lbox = SL / fmax(NP, 1.0);
            out[0] = (float)(lbox + CP / (double)NB + CN / (double)NB);
            g_ctr = 0;
        }
    }
}

// ---------------- launch ----------------
extern "C" void kernel_launch(void* const* d_in, const int* in_sizes, int n_in,
                              void* d_out, int out_size) {
    const float* preg = (const float*)d_in[0];
    const float* pcls = (const float*)d_in[1];
    const float* ancs = (const float*)d_in[2];
    const float* gbox = (const float*)d_in[3];
    const int*   glab = (const int*)d_in[4];
    float* out = (float*)d_out;

    dim3 grid(NBX, NB);
    k_match<<<grid, 256>>>(preg, pcls, ancs, gbox, glab);
    k_select<<<NB, 512>>>(out);
}

// round 5
// speedup vs baseline: 1.2925x; 1.2925x over previous
#include <cuda_runtime.h>
#include <math.h>

#define NB 64
#define NA 8732
#define NA4 2183            // NA/4 (exact)
#define NG 50
#define NC 21
#define NBX 35              // ceil(NA/256)
#define NWARP 16            // warps in k_select block
#define IOU_THR 0.5f
#define VXY 0.1f
#define VWH 0.2f
#define EPS16 9.765625e-4

// ---------------- device scratch (no allocations allowed) ----------------
__device__ float  g_lossneg[NB * NA];     // ce for negatives, -1 sentinel for positives
__device__ float  g_psl1[NB * NBX];
__device__ float  g_pce [NB * NBX];
__device__ int    g_pnp [NB * NBX];
__device__ double g_ob_cp[NB];
__device__ double g_ob_cn[NB];
__device__ double g_ob_np[NB];
__device__ double g_ob_sl[NB];
__device__ int    g_ctr;

// ---------------- helpers ----------------
__device__ __forceinline__ double warpRedD(double v) {
    #pragma unroll
    for (int o = 16; o > 0; o >>= 1) v += __shfl_down_sync(0xFFFFFFFFu, v, o);
    return v;
}
__device__ __forceinline__ float warpRedF(float v) {
    #pragma unroll
    for (int o = 16; o > 0; o >>= 1) v += __shfl_down_sync(0xFFFFFFFFu, v, o);
    return v;
}
__device__ __forceinline__ float smoothL1(float d) {
    float ad = fabsf(d);
    return ad < 1.0f ? 0.5f * d * d : ad - 0.5f;
}
__device__ __forceinline__ unsigned ordkey(float f) {
    unsigned u = __float_as_uint(f);
    return u ^ ((u >> 31) ? 0xFFFFFFFFu : 0x80000000u);
}
__device__ __forceinline__ float ordval(unsigned k) {
    unsigned u = (k & 0x80000000u) ? (k ^ 0x80000000u) : ~k;
    return __uint_as_float(u);
}

// ---------------- kernel 1: match + box loss + CE ----------------
__global__ __launch_bounds__(256) void k_match(const float* __restrict__ preg,
                        const float* __restrict__ pcls,
                        const float* __restrict__ ancs,
                        const float* __restrict__ gbox,
                        const int*   __restrict__ glab) {
    const int b = blockIdx.y;
    const int a = blockIdx.x * 256 + threadIdx.x;

    __shared__ float4 s_gb[NG];
    __shared__ float  s_ga[NG];
    __shared__ int    s_gl[NG];
    if (threadIdx.x < NG) {
        float4 gb = reinterpret_cast<const float4*>(gbox)[b * NG + threadIdx.x];
        int    gl = glab[b * NG + threadIdx.x];
        float  ag = (gb.z - gb.x) * (gb.w - gb.y);
        if (gl <= 0) { gb = make_float4(0.f, 0.f, 0.f, 0.f); ag = 0.f; }  // iou -> 0
        s_gb[threadIdx.x] = gb;
        s_ga[threadIdx.x] = ag;
        s_gl[threadIdx.x] = gl;
    }
    __syncthreads();

    float sl1_c = 0.f, ce_c = 0.f;
    int pos_c = 0;

    if (a < NA) {
        float4 anc = reinterpret_cast<const float4*>(ancs)[a];
        float al = anc.x - anc.z * 0.5f;
        float at = anc.y - anc.w * 0.5f;
        float ar = anc.x + anc.z * 0.5f;
        float ab = anc.y + anc.w * 0.5f;
        float area_a = (ar - al) * (ab - at);   // > 0 always

        // division-free IoU argmax: keep (inter, union) of current best
        float inb = -1.0f, unb = 1.0f;
        int   bi  = 0;
        #pragma unroll 10
        for (int g = 0; g < NG; g++) {
            float4 gb = s_gb[g];
            float ltx = fmaxf(gb.x, al), lty = fmaxf(gb.y, at);
            float rbx = fminf(gb.z, ar), rby = fminf(gb.w, ab);
            float w = fmaxf(rbx - ltx, 0.0f), h = fmaxf(rby - lty, 0.0f);
            float inter = w * h;
            float uni = s_ga[g] + area_a - inter;   // >= area_a > 0, clamp unnecessary
            if (inter * unb > inb * uni) { inb = inter; unb = uni; bi = g; }
        }
        bool pos = (2.0f * inb >= unb);   // iou >= 0.5

        float4 gb = s_gb[bi];
        float gcx = (gb.x + gb.z) * 0.5f, gcy = (gb.y + gb.w) * 0.5f;
        float gw = gb.z - gb.x, gh = gb.w - gb.y;
        float tx = (gcx - anc.x) / (anc.z * VXY);
        float ty = (gcy - anc.y) / (anc.w * VXY);
        float tw = __logf(fmaxf(gw, 1e-6f) / anc.z) * (1.0f / VWH);
        float th = __logf(fmaxf(gh, 1e-6f) / anc.w) * (1.0f / VWH);
        float d0 = preg[(b * 4 + 0) * NA + a] - tx;
        float d1 = preg[(b * 4 + 1) * NA + a] - ty;
        float d2 = preg[(b * 4 + 2) * NA + a] - tw;
        float d3 = preg[(b * 4 + 3) * NA + a] - th;
        float sl1 = smoothL1(d0) + smoothL1(d1) + smoothL1(d2) + smoothL1(d3);

        // CE: static-indexed register array; grab x[lab] via one re-load (L1 hit)
        const float* pc = pcls + (size_t)b * NC * NA + a;
        float m = -1e30f;
        float xs[NC];
        #pragma unroll
        for (int c = 0; c < NC; c++) {
            xs[c] = pc[c * NA];
            m = fmaxf(m, xs[c]);
        }
        float s = 0.0f;
        #pragma unroll
        for (int c = 0; c < NC; c++) s += __expf(xs[c] - m);
        float lse = m + __logf(s);
        int lab = pos ? s_gl[bi] : 0;
        float xlab = pc[lab * NA];              // avoids dynamic register indexing
        float ce = lse - xlab;

        g_lossneg[b * NA + a] = pos ? -1.0f : ce;
        if (pos) { pos_c = 1; ce_c = ce; sl1_c = sl1; }
    }

    sl1_c = warpRedF(sl1_c);
    ce_c  = warpRedF(ce_c);
    float posf = warpRedF((float)pos_c);
    __shared__ float sh0[8], sh1[8], sh2[8];
    int wid = threadIdx.x >> 5, lid = threadIdx.x & 31;
    if (lid == 0) { sh0[wid] = sl1_c; sh1[wid] = ce_c; sh2[wid] = posf; }
    __syncthreads();
    if (wid == 0) {
        float v0 = (lid < 8) ? sh0[lid] : 0.f;
        float v1 = (lid < 8) ? sh1[lid] : 0.f;
        float v2 = (lid < 8) ? sh2[lid] : 0.f;
        v0 = warpRedF(v0); v1 = warpRedF(v1); v2 = warpRedF(v2);
        if (lid == 0) {
            int p = b * NBX + blockIdx.x;
            g_psl1[p] = v0;
            g_pce [p] = v1;
            g_pnp [p] = (int)(v2 + 0.5f);
        }
    }
}

// ---------------- kernel 2: smem radix top-K with per-warp histograms ----------------
__global__ __launch_bounds__(512) void k_select(float* __restrict__ out) {
    const int b = blockIdx.x;
    const int tid = threadIdx.x;
    const int lane = tid & 31;
    const int wid = tid >> 5;

    __shared__ __align__(16) unsigned s_keys[NA];
    __shared__ unsigned hist[NWARP * 256];   // per-warp copies: hist[w*256 + bin]
    __shared__ unsigned s_suf[256];
    __shared__ unsigned s_wsum[8];
    __shared__ unsigned s_bin;
    __shared__ int s_rem;
    __shared__ double s_np, s_ce, s_sl;
    __shared__ int s_ticket;
    __shared__ double sd[16];

    unsigned* myh = &hist[wid * 256];

    // zero all histogram copies; warp 8 reduces per-block partials concurrently
    for (int i = tid; i < NWARP * 256; i += 512) hist[i] = 0;
    if (tid >= 256 && tid < 288) {
        int t = tid - 256;
        double np = 0.0, ce = 0.0, sl = 0.0;
        for (int i = t; i < NBX; i += 32) {
            int p = b * NBX + i;
            np += (double)g_pnp[p];
            ce += (double)g_pce[p];
            sl += (double)g_psl1[p];
        }
        np = warpRedD(np); ce = warpRedD(ce); sl = warpRedD(sl);
        if (t == 0) { s_np = np; s_ce = ce; s_sl = sl; }
    }
    __syncthreads();

    // pass 1: vectorized global read -> smem keys + top-byte per-warp histogram
    const float4* base4 = reinterpret_cast<const float4*>(&g_lossneg[b * NA]);
    uint4* keys4 = reinterpret_cast<uint4*>(s_keys);
    for (int i = tid; i < NA4; i += 512) {
        float4 v = base4[i];
        unsigned k0 = ordkey(v.x), k1 = ordkey(v.y), k2 = ordkey(v.z), k3 = ordkey(v.w);
        keys4[i] = make_uint4(k0, k1, k2, k3);
        atomicAdd(&myh[k0 >> 24], 1u);
        atomicAdd(&myh[k1 >> 24], 1u);
        atomicAdd(&myh[k2 >> 24], 1u);
        atomicAdd(&myh[k3 >> 24], 1u);
    }
    __syncthreads();

    int npos = (int)(s_np + 0.5);
    int numneg = NA - npos;
    int K = (npos > 0) ? min(3 * npos, numneg) : (numneg > 0 ? 1 : 0);

    double negsum = 0.0;
    if (K > 0) {
        unsigned prefix = 0, hmask = 0;
        int remaining = K;

        for (int shift = 24; shift >= 0; shift -= 8) {
            if (shift != 24) {
                for (int i = tid; i < NWARP * 256; i += 512) hist[i] = 0;
                __syncthreads();
                for (int i = tid; i < NA; i += 512) {
                    unsigned u = s_keys[i];
                    if ((u & hmask) == prefix)
                        atomicAdd(&myh[(u >> shift) & 255u], 1u);
                }
                __syncthreads();
            }

            // combine the 16 copies, then parallel inclusive suffix scan
            unsigned v = 0;
            if (tid < 256) {
                #pragma unroll
                for (int w = 0; w < NWARP; w++) v += hist[w * 256 + tid];
                #pragma unroll
                for (int d = 1; d < 32; d <<= 1) {
                    unsigned t = __shfl_down_sync(0xFFFFFFFFu, v, d);
                    if (lane + d < 32) v += t;
                }
                if (lane == 0) s_wsum[wid] = v;
            }
            __syncthreads();
            if (tid < 256) {
                unsigned e = 0;
                #pragma unroll
                for (int j = 0; j < 8; j++) if (j > wid) e += s_wsum[j];
                s_suf[tid] = v + e;
            }
            __syncthreads();
            if (tid < 256) {
                unsigned sufn = (tid < 255) ? s_suf[tid + 1] : 0u;
                unsigned suf  = s_suf[tid];
                unsigned rem  = (unsigned)remaining;
                if (sufn < rem && rem <= suf) { s_bin = (unsigned)tid; s_rem = (int)(rem - sufn); }
            }
            __syncthreads();
            prefix |= (s_bin << shift);
            hmask  |= (255u << shift);
            remaining = s_rem;
            __syncthreads();
        }

        unsigned pivot = prefix;
        float pv = ordval(pivot);

        double s = 0.0;
        for (int i = tid; i < NA; i += 512) {
            unsigned u = s_keys[i];
            if (u > pivot) s += (double)ordval(u);
        }
        s = warpRedD(s);
        if (lane == 0) sd[wid] = s;
        __syncthreads();
        if (tid < 32) {
            double t = (tid < 16) ? sd[tid] : 0.0;
            t = warpRedD(t);
            if (tid == 0) sd[0] = t + (double)remaining * (double)pv;
        }
        __syncthreads();
        negsum = sd[0];
    }

    if (tid == 0) {
        double nums = fmax(s_np, (double)EPS16);
        g_ob_cp[b] = s_ce / nums;
        g_ob_cn[b] = negsum / nums;
        g_ob_np[b] = s_np;
        g_ob_sl[b] = s_sl;
        __threadfence();
        s_ticket = atomicAdd(&g_ctr, 1);
    }
    __syncthreads();

    if (s_ticket == NB - 1) {
        double cp = 0.0, cn = 0.0, np = 0.0, sl = 0.0;
        if (tid < NB) {
            cp = g_ob_cp[tid]; cn = g_ob_cn[tid];
            np = g_ob_np[tid]; sl = g_ob_sl[tid];
        }
        cp = warpRedD(cp); cn = warpRedD(cn); np = warpRedD(np); sl = warpRedD(sl);
        __shared__ double f0[2], f1[2], f2[2], f3[2];
        if (lane == 0 && tid < NB) {
            f0[wid] = cp; f1[wid] = cn; f2[wid] = np; f3[wid] = sl;
        }
        __syncthreads();
        if (tid == 0) {
            double CP = f0[0] + f0[1];
            double CN = f1[0] + f1[1];
            double NP = f2[0] + f2[1];
            double SL = f3[0] + f3[1];
            double lbox = SL / fmax(NP, 1.0);
            out[0] = (float)(lbox + CP / (double)NB + CN / (double)NB);
            g_ctr = 0;
        }
    }
}

// ---------------- launch ----------------
extern "C" void kernel_launch(void* const* d_in, const int* in_sizes, int n_in,
                              void* d_out, int out_size) {
    const float* preg = (const float*)d_in[0];
    const float* pcls = (const float*)d_in[1];
    const float* ancs = (const float*)d_in[2];
    const float* gbox = (const float*)d_in[3];
    const int*   glab = (const int*)d_in[4];
    float* out = (float*)d_out;

    dim3 grid(NBX, NB);
    k_match<<<grid, 256>>>(preg, pcls, ancs, gbox, glab);
    k_select<<<NB, 512>>>(out);
}